// round 16
// baseline (speedup 1.0000x reference)
#include <cuda_runtime.h>
#include <cuda.h>
#include <cstdint>

// ============================ problem dims ============================
#define N_IMG 16
#define H_IMG 112
#define W_IMG 112
#define C_IN  256
#define C_OUT 256
#define H_PAD 114
#define W_PAD 114
static constexpr int TOTAL_POS = N_IMG * H_PAD * W_PAD;   // 207936 padded positions

// padded activations as int8: [pos][C_IN]  (~53 MB)
__device__ __align__(1024) uint8_t g_xp[(size_t)TOTAL_POS * C_IN];
// weights as int8, tap-major: [9][C_OUT][C_IN]
__device__ __align__(1024) uint8_t g_w8[9 * C_OUT * C_IN];

// ============================ fused pack kernel (R8-proven int8 packing) ============================
static constexpr int64_t XUNITS = (int64_t)TOTAL_POS * 64;
static constexpr int     WUNITS = 9 * C_OUT * 64;

__global__ void pack_kernel(const int* __restrict__ x, const int* __restrict__ w) {
    int64_t i = (int64_t)blockIdx.x * blockDim.x + threadIdx.x;
    if (i < XUNITS) {
        int c4 = (int)(i & 63);
        int64_t p = i >> 6;
        int wp = (int)(p % W_PAD);
        int64_t t = p / W_PAD;
        int hp = (int)(t % H_PAD);
        int n  = (int)(t / H_PAD);
        uint32_t word = 0;
        if (hp >= 1 && hp <= H_IMG && wp >= 1 && wp <= W_IMG) {
            const int4 v = *reinterpret_cast<const int4*>(
                x + ((((int64_t)n * H_IMG + (hp - 1)) * W_IMG + (wp - 1)) * C_IN + c4 * 4));
            word = (v.x & 255) | ((v.y & 255) << 8) | ((v.z & 255) << 16) | ((v.w & 255) << 24);
        }
        reinterpret_cast<uint32_t*>(g_xp)[i] = word;
    } else {
        int64_t j = i - XUNITS;
        if (j >= WUNITS) return;
        int c4 = (int)(j & 63);
        int t = (int)(j >> 6);
        int co = t % C_OUT;
        int tap = t / C_OUT;
        const int4 v = *reinterpret_cast<const int4*>(
            w + (((int64_t)co * 9 + tap) * C_IN + c4 * 4));
        reinterpret_cast<uint32_t*>(g_w8)[j] =
            (v.x & 255) | ((v.y & 255) << 8) | ((v.z & 255) << 16) | ((v.w & 255) << 24);
    }
}

// ============================ PTX helpers ============================
#define MBAR_INIT(addr, cnt) \
    asm volatile("mbarrier.init.shared.b64 [%0], %1;" :: "r"(addr), "r"(cnt) : "memory")
#define MBAR_EXPECT_TX(addr, bytes) \
    asm volatile("mbarrier.arrive.expect_tx.shared.b64 _, [%0], %1;" \
                 :: "r"(addr), "r"(bytes) : "memory")
#define MBAR_WAIT(addr, ph) do {                                             \
    uint32_t _m = (addr); uint32_t _p = (ph); uint32_t _d;                   \
    asm volatile("{\n\t.reg .pred p;\n\t"                                    \
        "mbarrier.try_wait.parity.acquire.cta.shared::cta.b64 p, [%1], %2;\n\t" \
        "selp.b32 %0, 1, 0, p;\n\t}"                                         \
        : "=r"(_d) : "r"(_m), "r"(_p) : "memory");                           \
    if (!_d) {                                                               \
        asm volatile("{\n\t.reg .pred P1;\n\t"                               \
            "WL_%=:\n\t"                                                     \
            "mbarrier.try_wait.parity.acquire.cta.shared::cta.b64 P1, [%0], %1, 0x989680;\n\t" \
            "@P1 bra.uni WD_%=;\n\t"                                         \
            "bra.uni WL_%=;\n\t"                                             \
            "WD_%=:\n\t}"                                                    \
            :: "r"(_m), "r"(_p) : "memory");                                 \
    } } while (0)
#define TMA2D(dst, map, cx, cy, mbar) \
    asm volatile("cp.async.bulk.tensor.2d.shared::cta.global.tile.mbarrier::complete_tx::bytes " \
                 "[%0], [%1, {%2, %3}], [%4];"                               \
                 :: "r"(dst), "l"(map), "r"(cx), "r"(cy), "r"(mbar) : "memory")

#define MMA_S8(d0, d1, d2, d3, a0, a1, a2, a3, b0, b1) \
    asm volatile("mma.sync.aligned.m16n8k32.row.col.s32.s8.s8.s32 " \
                 "{%0,%1,%2,%3}, {%4,%5,%6,%7}, {%8,%9}, {%0,%1,%2,%3};" \
                 : "+r"(d0), "+r"(d1), "+r"(d2), "+r"(d3) \
                 : "r"(a0), "r"(a1), "r"(a2), "r"(a3), "r"(b0), "r"(b1))

#define LDSM_X4(r0, r1, r2, r3, addr) \
    asm volatile("ldmatrix.sync.aligned.m8n8.x4.shared.b16 {%0,%1,%2,%3}, [%4];" \
                 : "=r"(r0), "=r"(r1), "=r"(r2), "=r"(r3) : "r"(addr))

// ============================ conv kernel ============================
// R15 structure (PASS @ 587us, tensor 76%) with the engine swapped to int8:
// identical 48KB stages (A 128x128B + B 256x128B), 4-stage TMA pipeline,
// 8 warps 2(M)x4(N), warp tile 64x64, identical ldmatrix addressing (an s8
// k32 slice occupies the same 32B/row as an fp16 k16 slice; the x4 map is
// byte-identical to the R8-proven s8 fragment coordinates). 18 chunks
// (9 taps x 2 ci-halves of 128 channels) -> HALF the MMA instructions.
// int32 accum; float32-value epilogue via __int2float_rn (R8-proven).
static constexpr int A_BYTES   = 128 * 128;                 // 16384
static constexpr int B_BYTES   = 256 * 128;                 // 32768
static constexpr int STAGE_B   = A_BYTES + B_BYTES;         // 49152
static constexpr int NSTAGES   = 4;
static constexpr int TILES_B   = NSTAGES * STAGE_B;         // 196608
static constexpr int SMEM_DYN  = 1024 + TILES_B + 64;
static constexpr int NCHUNKS   = 18;
static constexpr int NCTA      = (TOTAL_POS + 127) / 128;   // 1625

__global__ void __launch_bounds__(256, 1)
conv_kernel(const __grid_constant__ CUtensorMap mapA,
            const __grid_constant__ CUtensorMap mapB,
            float* __restrict__ out) {
    extern __shared__ uint8_t smraw[];
    const uint32_t sb = ((uint32_t)__cvta_generic_to_shared(smraw) + 1023u) & ~1023u;
    const uint32_t bar0 = sb + TILES_B;

    const int tid  = threadIdx.x;
    const int lane = tid & 31;
    const int wid  = tid >> 5;
    const int warp_m = wid >> 2;       // 0..1 (64 M rows each)
    const int wn     = wid & 3;        // 0..3 (64 couts each)
    const int g   = lane >> 2;
    const int tig = lane & 3;
    const int p0  = blockIdx.x * 128;  // first padded position of this CTA

    if (tid == 0) {
        #pragma unroll
        for (int i = 0; i < NSTAGES; i++) MBAR_INIT(bar0 + i * 8, 1);
    }
    __syncthreads();

    // ---------------- TMA issue helper (single thread) ----------------
    // chunk s: tap = s>>1 (kh*3+kw), half ch = s&1 (128 channels = 128B)
    auto issue = [&](int s) {
        const int slot = s % NSTAGES;
        const int tap = s >> 1, ch = s & 1;
        const int kh = tap / 3, kw = tap % 3;
        const uint32_t stg = sb + slot * STAGE_B;
        const uint32_t bar = bar0 + slot * 8;
        MBAR_EXPECT_TX(bar, (uint32_t)STAGE_B);
        TMA2D(stg,           &mapA, ch * 128, p0 + (kh - 1) * W_PAD + (kw - 1), bar);
        TMA2D(stg + A_BYTES, &mapB, ch * 128, tap * 256, bar);
    };

    if (tid == 0) { issue(0); issue(1); issue(2); }

    // ---------------- ldmatrix per-lane addressing (same bytes as R15) ----------------
    const uint32_t xm = (uint32_t)(lane & 7) << 4;            // SW128 XOR mask
    const uint32_t a_colsel = (uint32_t)((lane >> 4) << 4);   // 0 or 16
    uint32_t a_base[4];
    #pragma unroll
    for (int mb = 0; mb < 4; mb++)
        a_base[mb] = (uint32_t)((warp_m * 64 + mb * 16 + (lane & 15)) * 128);
    const uint32_t b_colsel = (uint32_t)((lane & 8) << 1);    // 0 or 16
    uint32_t b_base[4];
    #pragma unroll
    for (int q = 0; q < 4; q++)
        b_base[q] = (uint32_t)(A_BYTES +
            (wn * 64 + q * 16 + (lane & 7) + ((lane & 16) >> 1)) * 128);

    int d[4][8][4];
    #pragma unroll
    for (int mb = 0; mb < 4; mb++)
        #pragma unroll
        for (int nb = 0; nb < 8; nb++)
            #pragma unroll
            for (int q = 0; q < 4; q++) d[mb][nb][q] = 0;

    // ---------------- main loop ----------------
    #pragma unroll 1
    for (int c = 0; c < NCHUNKS; c++) {
        const int slot = c % NSTAGES;
        if (tid == 0 && c + NSTAGES - 1 < NCHUNKS) issue(c + NSTAGES - 1);
        MBAR_WAIT(bar0 + slot * 8, (c / NSTAGES) & 1);
        const uint32_t stg = sb + slot * STAGE_B;

        #pragma unroll
        for (int ks = 0; ks < 4; ks++) {      // 4 x k32 (32B) per 128B chunk
            const uint32_t cA = ((uint32_t)(ks * 32) + a_colsel) ^ xm;
            const uint32_t cB = ((uint32_t)(ks * 32) + b_colsel) ^ xm;
            uint32_t a[4][4];
            #pragma unroll
            for (int mb = 0; mb < 4; mb++)
                LDSM_X4(a[mb][0], a[mb][1], a[mb][2], a[mb][3],
                        stg + a_base[mb] + cA);
            uint32_t b[8][2];
            #pragma unroll
            for (int q = 0; q < 4; q++)
                LDSM_X4(b[2 * q][0], b[2 * q][1], b[2 * q + 1][0], b[2 * q + 1][1],
                        stg + b_base[q] + cB);
            #pragma unroll
            for (int mb = 0; mb < 4; mb++)
                #pragma unroll
                for (int nb = 0; nb < 8; nb++)
                    MMA_S8(d[mb][nb][0], d[mb][nb][1], d[mb][nb][2], d[mb][nb][3],
                           a[mb][0], a[mb][1], a[mb][2], a[mb][3],
                           b[nb][0], b[nb][1]);
        }

        __syncthreads();                     // all warps done with this slot
    }

    // ---------------- epilogue: mask invalid padded positions, store f32 ----------------
    #pragma unroll
    for (int mb = 0; mb < 4; mb++) {
        #pragma unroll
        for (int r = 0; r < 2; r++) {        // row g and g+8
            const int pos = p0 + warp_m * 64 + mb * 16 + g + r * 8;
            if (pos >= TOTAL_POS) continue;
            const int n  = pos / (H_PAD * W_PAD);
            const int rm = pos % (H_PAD * W_PAD);
            const int hp = rm / W_PAD;
            const int wp = rm % W_PAD;
            if (hp < 1 || hp > H_IMG || wp < 1 || wp > W_IMG) continue;
            const int64_t obase =
                (((int64_t)n * H_IMG + (hp - 1)) * W_IMG + (wp - 1)) * C_OUT;
            #pragma unroll
            for (int nb = 0; nb < 8; nb++) {
                const int co = wn * 64 + nb * 8 + tig * 2;
                *reinterpret_cast<float2*>(out + obase + co) =
                    make_float2(__int2float_rn(d[mb][nb][2 * r]),
                                __int2float_rn(d[mb][nb][2 * r + 1]));
            }
        }
    }
}

// ============================ host launch ============================
typedef CUresult (*TmapEncodeFn)(
    CUtensorMap*, CUtensorMapDataType, cuuint32_t, void*,
    const cuuint64_t*, const cuuint64_t*, const cuuint32_t*, const cuuint32_t*,
    CUtensorMapInterleave, CUtensorMapSwizzle, CUtensorMapL2promotion,
    CUtensorMapFloatOOBfill);

extern "C" void kernel_launch(void* const* d_in, const int* in_sizes, int n_in,
                              void* d_out, int out_size) {
    (void)out_size;
    // Bind inputs BY SIZE: x has 51,380,224 elements, weight has 589,824.
    const int* x = (const int*)d_in[0];
    const int* w = (const int*)d_in[1];
    if (n_in >= 2 && in_sizes[0] < in_sizes[1]) {
        x = (const int*)d_in[1];
        w = (const int*)d_in[0];
    }
    float* out = (float*)d_out;

    const int64_t total_units = XUNITS + WUNITS;
    pack_kernel<<<(unsigned)((total_units + 255) / 256), 256>>>(x, w);

    // tensormaps
    void* xp = nullptr; void* wp = nullptr;
    cudaGetSymbolAddress(&xp, g_xp);
    cudaGetSymbolAddress(&wp, g_w8);

    TmapEncodeFn enc = nullptr;
    cudaDriverEntryPointQueryResult qres;
    cudaGetDriverEntryPointByVersion("cuTensorMapEncodeTiled", (void**)&enc,
                                     12000, cudaEnableDefault, &qres);

    CUtensorMap mapA, mapB;
    {
        cuuint64_t dims[2]    = {C_IN, (cuuint64_t)TOTAL_POS};
        cuuint64_t strides[1] = {C_IN};                       // bytes
        cuuint32_t box[2]     = {128, 128};
        cuuint32_t es[2]      = {1, 1};
        enc(&mapA, CU_TENSOR_MAP_DATA_TYPE_UINT8, 2, xp, dims, strides, box, es,
            CU_TENSOR_MAP_INTERLEAVE_NONE, CU_TENSOR_MAP_SWIZZLE_128B,
            CU_TENSOR_MAP_L2_PROMOTION_L2_128B, CU_TENSOR_MAP_FLOAT_OOB_FILL_NONE);
    }
    {
        cuuint64_t dims[2]    = {C_IN, 9 * C_OUT};
        cuuint64_t strides[1] = {C_IN};
        cuuint32_t box[2]     = {128, 256};
        cuuint32_t es[2]      = {1, 1};
        enc(&mapB, CU_TENSOR_MAP_DATA_TYPE_UINT8, 2, wp, dims, strides, box, es,
            CU_TENSOR_MAP_INTERLEAVE_NONE, CU_TENSOR_MAP_SWIZZLE_128B,
            CU_TENSOR_MAP_L2_PROMOTION_L2_128B, CU_TENSOR_MAP_FLOAT_OOB_FILL_NONE);
    }

    cudaFuncSetAttribute(conv_kernel, cudaFuncAttributeMaxDynamicSharedMemorySize, SMEM_DYN);
    conv_kernel<<<NCTA, 256, SMEM_DYN>>>(mapA, mapB, out);
}

// round 17
// speedup vs baseline: 3.2213x; 3.2213x over previous
#include <cuda_runtime.h>
#include <cuda_fp16.h>
#include <cuda.h>
#include <cstdint>

// ============================ problem dims ============================
#define N_IMG 16
#define H_IMG 112
#define W_IMG 112
#define C_IN  256
#define C_OUT 256
#define H_PAD 114
#define W_PAD 114
static constexpr int TOTAL_POS = N_IMG * H_PAD * W_PAD;   // 207936 padded positions

// padded activations as fp16: [pos][C_IN]  (~106 MB)
__device__ __align__(1024) __half g_xh[(size_t)TOTAL_POS * C_IN];
// weights as fp16, tap-major: [9][C_OUT][C_IN]
__device__ __align__(1024) __half g_wh[9 * C_OUT * C_IN];

// ============================ fused pack kernel (proven) ============================
static constexpr int64_t XUNITS = (int64_t)TOTAL_POS * 64;
static constexpr int     WUNITS = 9 * C_OUT * 64;

__global__ void pack_kernel(const int* __restrict__ x, const int* __restrict__ w) {
    int64_t i = (int64_t)blockIdx.x * blockDim.x + threadIdx.x;
    if (i < XUNITS) {
        int c4 = (int)(i & 63);
        int64_t p = i >> 6;
        int wp = (int)(p % W_PAD);
        int64_t t = p / W_PAD;
        int hp = (int)(t % H_PAD);
        int n  = (int)(t / H_PAD);
        uint2 wout = make_uint2(0u, 0u);
        if (hp >= 1 && hp <= H_IMG && wp >= 1 && wp <= W_IMG) {
            const int4 v = *reinterpret_cast<const int4*>(
                x + ((((int64_t)n * H_IMG + (hp - 1)) * W_IMG + (wp - 1)) * C_IN + c4 * 4));
            __half2 p0 = __floats2half2_rn((float)v.x, (float)v.y);
            __half2 p1 = __floats2half2_rn((float)v.z, (float)v.w);
            wout.x = *reinterpret_cast<uint32_t*>(&p0);
            wout.y = *reinterpret_cast<uint32_t*>(&p1);
        }
        reinterpret_cast<uint2*>(g_xh)[i] = wout;
    } else {
        int64_t j = i - XUNITS;
        if (j >= WUNITS) return;
        int c4 = (int)(j & 63);
        int t = (int)(j >> 6);
        int co = t % C_OUT;
        int tap = t / C_OUT;
        const int4 v = *reinterpret_cast<const int4*>(
            w + (((int64_t)co * 9 + tap) * C_IN + c4 * 4));
        __half2 p0 = __floats2half2_rn((float)v.x, (float)v.y);
        __half2 p1 = __floats2half2_rn((float)v.z, (float)v.w);
        reinterpret_cast<uint2*>(g_wh)[j] = make_uint2(
            *reinterpret_cast<uint32_t*>(&p0), *reinterpret_cast<uint32_t*>(&p1));
    }
}

// ============================ PTX helpers ============================
#define MBAR_INIT(addr, cnt) \
    asm volatile("mbarrier.init.shared.b64 [%0], %1;" :: "r"(addr), "r"(cnt) : "memory")
#define MBAR_EXPECT_TX(addr, bytes) \
    asm volatile("mbarrier.arrive.expect_tx.shared.b64 _, [%0], %1;" \
                 :: "r"(addr), "r"(bytes) : "memory")
#define MBAR_ARRIVE(addr) \
    asm volatile("mbarrier.arrive.release.cta.shared::cta.b64 _, [%0];" \
                 :: "r"(addr) : "memory")
#define MBAR_WAIT(addr, ph) do {                                             \
    uint32_t _m = (addr); uint32_t _p = (ph); uint32_t _d;                   \
    asm volatile("{\n\t.reg .pred p;\n\t"                                    \
        "mbarrier.try_wait.parity.acquire.cta.shared::cta.b64 p, [%1], %2;\n\t" \
        "selp.b32 %0, 1, 0, p;\n\t}"                                         \
        : "=r"(_d) : "r"(_m), "r"(_p) : "memory");                           \
    if (!_d) {                                                               \
        asm volatile("{\n\t.reg .pred P1;\n\t"                               \
            "WL_%=:\n\t"                                                     \
            "mbarrier.try_wait.parity.acquire.cta.shared::cta.b64 P1, [%0], %1, 0x989680;\n\t" \
            "@P1 bra.uni WD_%=;\n\t"                                         \
            "bra.uni WL_%=;\n\t"                                             \
            "WD_%=:\n\t}"                                                    \
            :: "r"(_m), "r"(_p) : "memory");                                 \
    } } while (0)
#define TMA2D(dst, map, cx, cy, mbar) \
    asm volatile("cp.async.bulk.tensor.2d.shared::cta.global.tile.mbarrier::complete_tx::bytes " \
                 "[%0], [%1, {%2, %3}], [%4];"                               \
                 :: "r"(dst), "l"(map), "r"(cx), "r"(cy), "r"(mbar) : "memory")

#define MMA_F16(d0, d1, d2, d3, a0, a1, a2, a3, b0, b1) \
    asm volatile("mma.sync.aligned.m16n8k16.row.col.f32.f16.f16.f32 " \
                 "{%0,%1,%2,%3}, {%4,%5,%6,%7}, {%8,%9}, {%0,%1,%2,%3};" \
                 : "+f"(d0), "+f"(d1), "+f"(d2), "+f"(d3) \
                 : "r"(a0), "r"(a1), "r"(a2), "r"(a3), "r"(b0), "r"(b1))

#define LDSM_X4(r0, r1, r2, r3, addr) \
    asm volatile("ldmatrix.sync.aligned.m8n8.x4.shared.b16 {%0,%1,%2,%3}, [%4];" \
                 : "=r"(r0), "=r"(r1), "=r"(r2), "=r"(r3) : "r"(addr))

// ============================ conv kernel ============================
// R15 structure (PASS @ 587us, tensor 76.1%) with decoupled warp scheduling:
//  - NO __syncthreads in the main loop. Per-slot "empty" mbarriers (arrive
//    count 8 = one per warp) let warps spread up to ~2 chunks apart, so the
//    two warps per SMSP cover each other's boundary stalls.
//  - Fragment double-buffering across ks: LDSM for ks+1 issued before the 32
//    HMMA of ks, removing the load->mma ramp at every k-step.
// Everything else identical: CTA = 128 padded positions x 256 couts, fp16
// m16n8k16, 48KB stages, 4-stage TMA pipeline, float32-value epilogue.
static constexpr int A_BYTES   = 128 * 128;                 // 16384
static constexpr int B_BYTES   = 256 * 128;                 // 32768
static constexpr int STAGE_B   = A_BYTES + B_BYTES;         // 49152
static constexpr int NSTAGES   = 4;
static constexpr int TILES_B   = NSTAGES * STAGE_B;         // 196608
static constexpr int SMEM_DYN  = 1024 + TILES_B + 128;
static constexpr int NCHUNKS   = 36;
static constexpr int NCTA      = (TOTAL_POS + 127) / 128;   // 1625

__global__ void __launch_bounds__(256, 1)
conv_kernel(const __grid_constant__ CUtensorMap mapA,
            const __grid_constant__ CUtensorMap mapB,
            float* __restrict__ out) {
    extern __shared__ uint8_t smraw[];
    const uint32_t sb = ((uint32_t)__cvta_generic_to_shared(smraw) + 1023u) & ~1023u;
    const uint32_t full0  = sb + TILES_B;           // full[i]  = full0 + i*8
    const uint32_t empty0 = sb + TILES_B + 32;      // empty[i] = empty0 + i*8

    const int tid  = threadIdx.x;
    const int lane = tid & 31;
    const int wid  = tid >> 5;
    const int warp_m = wid >> 2;       // 0..1 (64 M rows each)
    const int wn     = wid & 3;        // 0..3 (64 couts each)
    const int g   = lane >> 2;
    const int tig = lane & 3;
    const int p0  = blockIdx.x * 128;  // first padded position of this CTA

    if (tid == 0) {
        #pragma unroll
        for (int i = 0; i < NSTAGES; i++) {
            MBAR_INIT(full0 + i * 8, 1);
            MBAR_INIT(empty0 + i * 8, 8);
        }
    }
    __syncthreads();

    // ---------------- TMA issue helper (single thread) ----------------
    // chunk s: tap = s>>2 (kh*3+kw), quarter ch = s&3 (64 fp16 ch = 128B)
    auto issue = [&](int s) {
        const int slot = s % NSTAGES;
        const int tap = s >> 2, ch = s & 3;
        const int kh = tap / 3, kw = tap % 3;
        const uint32_t stg = sb + slot * STAGE_B;
        const uint32_t bar = full0 + slot * 8;
        MBAR_EXPECT_TX(bar, (uint32_t)STAGE_B);
        TMA2D(stg,           &mapA, ch * 64, p0 + (kh - 1) * W_PAD + (kw - 1), bar);
        TMA2D(stg + A_BYTES, &mapB, ch * 64, tap * 256, bar);
    };

    if (tid == 0) { issue(0); issue(1); issue(2); }

    // ---------------- ldmatrix per-lane addressing (R15-proven) ----------------
    const uint32_t xm = (uint32_t)(lane & 7) << 4;            // SW128 XOR mask
    const uint32_t a_colsel = (uint32_t)((lane >> 4) << 4);   // 0 or 16
    uint32_t a_base[4];
    #pragma unroll
    for (int mb = 0; mb < 4; mb++)
        a_base[mb] = (uint32_t)((warp_m * 64 + mb * 16 + (lane & 15)) * 128);
    const uint32_t b_colsel = (uint32_t)((lane & 8) << 1);    // 0 or 16
    uint32_t b_base[4];
    #pragma unroll
    for (int q = 0; q < 4; q++)
        b_base[q] = (uint32_t)(A_BYTES +
            (wn * 64 + q * 16 + (lane & 7) + ((lane & 16) >> 1)) * 128);

    float d[4][8][4];
    #pragma unroll
    for (int mb = 0; mb < 4; mb++)
        #pragma unroll
        for (int nb = 0; nb < 8; nb++)
            #pragma unroll
            for (int q = 0; q < 4; q++) d[mb][nb][q] = 0.0f;

    // fragment double buffers
    uint32_t a[2][4][4];
    uint32_t b[2][8][2];

    auto load_frags = [&](int buf, uint32_t stg, int ks) {
        const uint32_t cA = ((uint32_t)(ks * 32) + a_colsel) ^ xm;
        const uint32_t cB = ((uint32_t)(ks * 32) + b_colsel) ^ xm;
        #pragma unroll
        for (int mb = 0; mb < 4; mb++)
            LDSM_X4(a[buf][mb][0], a[buf][mb][1], a[buf][mb][2], a[buf][mb][3],
                    stg + a_base[mb] + cA);
        #pragma unroll
        for (int q = 0; q < 4; q++)
            LDSM_X4(b[buf][2 * q][0], b[buf][2 * q][1],
                    b[buf][2 * q + 1][0], b[buf][2 * q + 1][1],
                    stg + b_base[q] + cB);
    };

    // ---------------- main loop (no CTA-wide barrier) ----------------
    #pragma unroll 1
    for (int c = 0; c < NCHUNKS; c++) {
        const int slot = c % NSTAGES;
        // producer: re-issue into slot (c+3)%4 once all warps freed it
        if (tid == 0 && c + NSTAGES - 1 < NCHUNKS) {
            const int s = c + NSTAGES - 1;
            if (s >= NSTAGES)   // slot previously consumed by chunk s-4
                MBAR_WAIT(empty0 + (s % NSTAGES) * 8, (((s - NSTAGES) / NSTAGES) & 1));
            issue(s);
        }
        MBAR_WAIT(full0 + slot * 8, (c / NSTAGES) & 1);
        const uint32_t stg = sb + slot * STAGE_B;

        load_frags(0, stg, 0);
        #pragma unroll
        for (int ks = 0; ks < 4; ks++) {
            if (ks < 3) load_frags((ks + 1) & 1, stg, ks + 1);
            const int buf = ks & 1;
            #pragma unroll
            for (int mb = 0; mb < 4; mb++)
                #pragma unroll
                for (int nb = 0; nb < 8; nb++)
                    MMA_F16(d[mb][nb][0], d[mb][nb][1], d[mb][nb][2], d[mb][nb][3],
                            a[buf][mb][0], a[buf][mb][1], a[buf][mb][2], a[buf][mb][3],
                            b[buf][nb][0], b[buf][nb][1]);
        }

        // this warp is done reading slot: release it
        if (lane == 0) MBAR_ARRIVE(empty0 + slot * 8);
    }

    // ---------------- epilogue: mask invalid padded positions, store f32 ----------------
    #pragma unroll
    for (int mb = 0; mb < 4; mb++) {
        #pragma unroll
        for (int r = 0; r < 2; r++) {        // row g and g+8
            const int pos = p0 + warp_m * 64 + mb * 16 + g + r * 8;
            if (pos >= TOTAL_POS) continue;
            const int n  = pos / (H_PAD * W_PAD);
            const int rm = pos % (H_PAD * W_PAD);
            const int hp = rm / W_PAD;
            const int wp = rm % W_PAD;
            if (hp < 1 || hp > H_IMG || wp < 1 || wp > W_IMG) continue;
            const int64_t obase =
                (((int64_t)n * H_IMG + (hp - 1)) * W_IMG + (wp - 1)) * C_OUT;
            #pragma unroll
            for (int nb = 0; nb < 8; nb++) {
                const int co = wn * 64 + nb * 8 + tig * 2;
                *reinterpret_cast<float2*>(out + obase + co) =
                    make_float2(d[mb][nb][2 * r], d[mb][nb][2 * r + 1]);
            }
        }
    }
}

// ============================ host launch ============================
typedef CUresult (*TmapEncodeFn)(
    CUtensorMap*, CUtensorMapDataType, cuuint32_t, void*,
    const cuuint64_t*, const cuuint64_t*, const cuuint32_t*, const cuuint32_t*,
    CUtensorMapInterleave, CUtensorMapSwizzle, CUtensorMapL2promotion,
    CUtensorMapFloatOOBfill);

extern "C" void kernel_launch(void* const* d_in, const int* in_sizes, int n_in,
                              void* d_out, int out_size) {
    (void)out_size;
    // Bind inputs BY SIZE: x has 51,380,224 elements, weight has 589,824.
    const int* x = (const int*)d_in[0];
    const int* w = (const int*)d_in[1];
    if (n_in >= 2 && in_sizes[0] < in_sizes[1]) {
        x = (const int*)d_in[1];
        w = (const int*)d_in[0];
    }
    float* out = (float*)d_out;

    const int64_t total_units = XUNITS + WUNITS;
    pack_kernel<<<(unsigned)((total_units + 255) / 256), 256>>>(x, w);

    // tensormaps
    void* xp = nullptr; void* wp = nullptr;
    cudaGetSymbolAddress(&xp, g_xh);
    cudaGetSymbolAddress(&wp, g_wh);

    TmapEncodeFn enc = nullptr;
    cudaDriverEntryPointQueryResult qres;
    cudaGetDriverEntryPointByVersion("cuTensorMapEncodeTiled", (void**)&enc,
                                     12000, cudaEnableDefault, &qres);

    CUtensorMap mapA, mapB;
    {
        cuuint64_t dims[2]    = {C_IN, (cuuint64_t)TOTAL_POS};
        cuuint64_t strides[1] = {C_IN * 2};                   // bytes
        cuuint32_t box[2]     = {64, 128};
        cuuint32_t es[2]      = {1, 1};
        enc(&mapA, CU_TENSOR_MAP_DATA_TYPE_FLOAT16, 2, xp, dims, strides, box, es,
            CU_TENSOR_MAP_INTERLEAVE_NONE, CU_TENSOR_MAP_SWIZZLE_128B,
            CU_TENSOR_MAP_L2_PROMOTION_L2_128B, CU_TENSOR_MAP_FLOAT_OOB_FILL_NONE);
    }
    {
        cuuint64_t dims[2]    = {C_IN, 9 * C_OUT};
        cuuint64_t strides[1] = {C_IN * 2};
        cuuint32_t box[2]     = {64, 256};
        cuuint32_t es[2]      = {1, 1};
        enc(&mapB, CU_TENSOR_MAP_DATA_TYPE_FLOAT16, 2, wp, dims, strides, box, es,
            CU_TENSOR_MAP_INTERLEAVE_NONE, CU_TENSOR_MAP_SWIZZLE_128B,
            CU_TENSOR_MAP_L2_PROMOTION_L2_128B, CU_TENSOR_MAP_FLOAT_OOB_FILL_NONE);
    }

    cudaFuncSetAttribute(conv_kernel, cudaFuncAttributeMaxDynamicSharedMemorySize, SMEM_DYN);
    conv_kernel<<<NCTA, 256, SMEM_DYN>>>(mapA, mapB, out);
}